// round 10
// baseline (speedup 1.0000x reference)
#include <cuda_runtime.h>
#include <cuda_bf16.h>
#include <cstddef>

// Problem constants (fixed shapes per reference)
constexpr int B_ = 16;
constexpr int C_ = 256;
constexpr int L_ = 8192;
constexpr int D_ = 512;   // d_inner
constexpr int A_ = 64;    // att_dim

constexpr int GRID_MAIN = 1024;
constexpr int TILES_PB  = (B_ * (L_ / 16)) / GRID_MAIN;  // 8 tiles of 16 l's

// Single fused kernel. Each block:
//   1) computes coef = <wq,wk>/8 (warp 0) and u[512] = w_out @ wv ONCE,
//      with fully coalesced loads (thread t reads w_out4[it*256+t]) and
//      16-lane shuffle reduction -> amortized over 8 tiles, L1-friendly.
//   2) processes 8 tiles of (b, 16 l) in the proven R8 structure: h_v read
//      exactly once into registers, two smem reductions, float4 streaming
//      stores of the 512x16 output tile.
__global__ void __launch_bounds__(256, 6)
fused_kernel(const float* __restrict__ h_v,
             const float* __restrict__ wq,
             const float* __restrict__ wk,
             const float* __restrict__ wv,
             const float* __restrict__ w_out,
             float* __restrict__ out) {
    __shared__ float s_u[D_];
    __shared__ float s_red[256];
    __shared__ float s_red2[256];
    __shared__ float s_sval[16];
    __shared__ __align__(16) float s_pooled[16];
    __shared__ float s_coef;

    const int tid = threadIdx.x;
    const int ll  = tid & 15;   // l within tile
    const int cg  = tid >> 4;   // c-group 0..15 (16 c each)

    // ---- coef (warp 0) ----
    if (tid < 32) {
        float p = wq[tid] * wk[tid] + wq[tid + 32] * wk[tid + 32];
#pragma unroll
        for (int m = 16; m >= 1; m >>= 1)
            p += __shfl_xor_sync(0xffffffffu, p, m);
        if (tid == 0) s_coef = p * 0.125f;  // 1/sqrt(64)
    }

    // ---- u[d] = w_out @ wv, coalesced, once per block ----
    {
        const int q = tid & 15;                 // float4-chunk within row
        const float4 vv = reinterpret_cast<const float4*>(wv)[q];  // loop-invariant
        const float4* w4 = reinterpret_cast<const float4*>(w_out);
#pragma unroll 4
        for (int it = 0; it < 32; it++) {
            float4 r = __ldg(&w4[it * 256 + tid]);
            float acc = r.x * vv.x + r.y * vv.y + r.z * vv.z + r.w * vv.w;
            // reduce over the 16-lane group (q = lane&15)
            acc += __shfl_xor_sync(0xffffffffu, acc, 8);
            acc += __shfl_xor_sync(0xffffffffu, acc, 4);
            acc += __shfl_xor_sync(0xffffffffu, acc, 2);
            acc += __shfl_xor_sync(0xffffffffu, acc, 1);
            if (q == 0) s_u[it * 16 + (tid >> 4)] = acc;
        }
    }
    __syncthreads();
    const float coef = s_coef;

    const int bk = blockIdx.x;

#pragma unroll 1
    for (int tt = 0; tt < TILES_PB; tt++) {
        const int tile   = bk + tt * GRID_MAIN;   // resident blocks contiguous
        const int b      = tile >> 9;
        const int l_base = (tile & 511) << 4;

        // ---- single read of h_v: 16 values per thread ----
        const float* p = h_v + ((size_t)b * C_ + (size_t)cg * 16) * L_ + l_base + ll;
        float h[16];
#pragma unroll
        for (int i = 0; i < 16; i++) h[i] = __ldcs(p + (size_t)i * L_);

        // ---- mean over C ----
        float sum = 0.f;
#pragma unroll
        for (int i = 0; i < 16; i++) sum += h[i];
        s_red[tid] = sum;
        __syncthreads();
        if (tid < 16) {
            float t = 0.f;
#pragma unroll
            for (int j = 0; j < 16; j++) t += s_red[tid + 16 * j];
            s_sval[tid] = t * ((1.0f / 256.0f) * coef);
        }
        __syncthreads();

        const float coef2 = s_sval[ll];

        // ---- softmax-weighted sum (max-free: |logit| bounded ~1.2) ----
        float se = 0.f, seh = 0.f;
#pragma unroll
        for (int i = 0; i < 16; i++) {
            float e = __expf(h[i] * coef2);
            se  += e;
            seh += e * h[i];
        }
        s_red[tid]  = se;
        s_red2[tid] = seh;
        __syncthreads();
        if (tid < 16) {
            float te = 0.f, teh = 0.f;
#pragma unroll
            for (int j = 0; j < 16; j++) {
                te  += s_red[tid + 16 * j];
                teh += s_red2[tid + 16 * j];
            }
            s_pooled[tid] = teh / te;
        }
        __syncthreads();

        // ---- epilogue: out[b,d,l] = pooled[l] * u[d], float4 streaming stores
        const int lq = tid & 3;
        const int d0 = tid >> 2;
        const float4 pv = reinterpret_cast<const float4*>(s_pooled)[lq];
        float4* out4 = reinterpret_cast<float4*>(out + (size_t)b * D_ * L_ + l_base) + lq;
#pragma unroll
        for (int k = 0; k < 8; k++) {
            int d = d0 + 64 * k;
            float ud = s_u[d];
            __stcs(&out4[(size_t)d * (L_ / 4)],
                   make_float4(pv.x * ud, pv.y * ud, pv.z * ud, pv.w * ud));
        }
        __syncthreads();  // protect s_red/s_pooled reuse next tile
    }
}

extern "C" void kernel_launch(void* const* d_in, const int* in_sizes, int n_in,
                              void* d_out, int out_size) {
    const float* h_v   = (const float*)d_in[0];  // [B, C, L]
    const float* wq    = (const float*)d_in[1];  // [64]
    const float* wk    = (const float*)d_in[2];  // [64]
    const float* wv    = (const float*)d_in[3];  // [64]
    const float* w_out = (const float*)d_in[4];  // [512, 64]
    float* out = (float*)d_out;                  // [B, 512, L]

    fused_kernel<<<GRID_MAIN, 256>>>(h_v, wq, wk, wv, w_out, out);
}

// round 11
// speedup vs baseline: 1.2805x; 1.2805x over previous
#include <cuda_runtime.h>
#include <cuda_bf16.h>
#include <cstddef>

// Problem constants (fixed shapes per reference)
constexpr int B_ = 16;
constexpr int C_ = 256;
constexpr int L_ = 8192;
constexpr int D_ = 512;   // d_inner
constexpr int A_ = 64;    // att_dim

// Scratch: u[d] = sum_a w_out[d,a]*wv[a]; coef = <wq,wk>/sqrt(att_dim)
__device__ float g_u[D_];
__device__ float g_coef;

// Fast prep: 128 blocks x 256 threads. Global thread i handles float4 chunk i
// of w_out (8192 chunks total = 512 rows x 16 chunks). Fully coalesced single
// LDG per thread, 16-lane shuffle reduce, one STG per row.
__global__ void prep_kernel(const float* __restrict__ wq,
                            const float* __restrict__ wk,
                            const float* __restrict__ wv,
                            const float* __restrict__ w_out) {
    const int t   = threadIdx.x;
    const int idx = blockIdx.x * 256 + t;      // 0..8191 float4 chunks
    const int q   = idx & 15;                  // chunk within row
    const int row = idx >> 4;                  // d row

    const float4 vv = reinterpret_cast<const float4*>(wv)[q];
    const float4 r  = reinterpret_cast<const float4*>(w_out)[idx];
    float acc = r.x * vv.x + r.y * vv.y + r.z * vv.z + r.w * vv.w;
    // reduce across the 16-lane group (q == lane&15)
    acc += __shfl_xor_sync(0xffffffffu, acc, 8);
    acc += __shfl_xor_sync(0xffffffffu, acc, 4);
    acc += __shfl_xor_sync(0xffffffffu, acc, 2);
    acc += __shfl_xor_sync(0xffffffffu, acc, 1);
    if (q == 0) g_u[row] = acc;

    // coef: block 0, warp 0
    if (blockIdx.x == 0 && t < 32) {
        float p = wq[t] * wk[t] + wq[t + 32] * wk[t + 32];
#pragma unroll
        for (int m = 16; m >= 1; m >>= 1)
            p += __shfl_xor_sync(0xffffffffu, p, m);
        if (t == 0) g_coef = p * 0.125f;  // 1/sqrt(64)
    }
}

// Main kernel: R8 structure, unchanged (61.0us, measured x3).
// One block = (one b, 16 consecutive l). 256 threads = 16 c-groups x 16 l.
// Each thread keeps 16 h values in registers -> h_v read exactly once.
__global__ void __launch_bounds__(256, 6)
pool_outer_kernel(const float* __restrict__ h_v, float* __restrict__ out) {
    __shared__ float s_u[D_];
    __shared__ float s_red[256];
    __shared__ float s_red2[256];
    __shared__ float s_sval[16];
    __shared__ __align__(16) float s_pooled[16];

    const int tid = threadIdx.x;
    const int ll  = tid & 15;   // l within tile
    const int cg  = tid >> 4;   // c-group 0..15 (16 c each)

    const int bidx   = blockIdx.x;          // 16 * 512 = 8192 blocks
    const int b      = bidx >> 9;
    const int l_base = (bidx & 511) << 4;

    const float coef = g_coef;

    // stage u into smem (2 per thread)
    s_u[tid]       = g_u[tid];
    s_u[tid + 256] = g_u[tid + 256];

    // ---- single read of h_v: 16 values per thread (imm-offset LDGs) ----
    const float* p = h_v + ((size_t)b * C_ + (size_t)cg * 16) * L_ + l_base + ll;
    float h[16];
#pragma unroll
    for (int i = 0; i < 16; i++) h[i] = __ldcs(p + (size_t)i * L_);

    // ---- mean over C ----
    float sum = 0.f;
#pragma unroll
    for (int i = 0; i < 16; i++) sum += h[i];
    s_red[tid] = sum;
    __syncthreads();
    if (tid < 16) {
        float t = 0.f;
#pragma unroll
        for (int j = 0; j < 16; j++) t += s_red[tid + 16 * j];
        s_sval[tid] = t * ((1.0f / 256.0f) * coef);  // fold mean scale + qk/sqrt(A)
    }
    __syncthreads();

    const float coef2 = s_sval[ll];  // per-l logit scale

    // ---- softmax-weighted sum (max-free: |logit| bounded ~1.2) ----
    float se = 0.f, seh = 0.f;
#pragma unroll
    for (int i = 0; i < 16; i++) {
        float e = __expf(h[i] * coef2);
        se  += e;
        seh += e * h[i];
    }
    s_red[tid]  = se;
    s_red2[tid] = seh;
    __syncthreads();
    if (tid < 16) {
        float te = 0.f, teh = 0.f;
#pragma unroll
        for (int j = 0; j < 16; j++) {
            te  += s_red[tid + 16 * j];
            teh += s_red2[tid + 16 * j];
        }
        s_pooled[tid] = teh / te;
    }
    __syncthreads();

    // ---- epilogue: out[b,d,l] = pooled[l] * u[d], float4 streaming stores.
    const int lq = tid & 3;
    const int d0 = tid >> 2;
    const float4 pv = reinterpret_cast<const float4*>(s_pooled)[lq];
    float4* out4 = reinterpret_cast<float4*>(out + (size_t)b * D_ * L_ + l_base) + lq;
#pragma unroll
    for (int k = 0; k < 8; k++) {
        int d = d0 + 64 * k;
        float ud = s_u[d];
        __stcs(&out4[(size_t)d * (L_ / 4)],
               make_float4(pv.x * ud, pv.y * ud, pv.z * ud, pv.w * ud));
    }
}

extern "C" void kernel_launch(void* const* d_in, const int* in_sizes, int n_in,
                              void* d_out, int out_size) {
    const float* h_v   = (const float*)d_in[0];  // [B, C, L]
    const float* wq    = (const float*)d_in[1];  // [64]
    const float* wk    = (const float*)d_in[2];  // [64]
    const float* wv    = (const float*)d_in[3];  // [64]
    const float* w_out = (const float*)d_in[4];  // [512, 64]
    float* out = (float*)d_out;                  // [B, 512, L]

    prep_kernel<<<(D_ * A_ / 4) / 256, 256>>>(wq, wk, wv, w_out);
    pool_outer_kernel<<<B_ * (L_ / 16), 256>>>(h_v, out);
}